// round 16
// baseline (speedup 1.0000x reference)
#include <cuda_runtime.h>
#include <cstdint>

// QuantileLoss: mean over [N,5] loss built from preds[N,5], target[N,3].
// R16: per-warp double-buffered cp.async pipeline — NO block barriers in the
//      mainloop (the __syncthreads coupling is what killed R5/R6/R8).
//      Each warp owns 2x2KB smem buffers (16 quads/stage), pipelines with
//      wait_group 1 + __syncwarp only. 256-thr blocks, 32KB smem -> 6 blk/SM,
//      48 warps (75% occ), every warp always has a stage in flight.
//      Epilogue: proven zero-kernel + one atomicAdd per block.

__global__ void zero_out_kernel(float* out) {
    if (threadIdx.x == 0) out[0] = 0.0f;
}

__device__ __forceinline__ void cp_async16(uint32_t saddr, const void* gptr) {
    asm volatile("cp.async.cg.shared.global [%0], [%1], 16;\n"
                 :: "r"(saddr), "l"(gptr));
}

__device__ __forceinline__ float row_loss(
    float p0, float p1, float p2, float p3, float p4,
    float t0, float t1, float t2)
{
    float d0 = p0 - t0;
    float d1 = p1 - t1;
    float d2 = p2 - t2;
    float main_mse = d0 * d0 + d1 * d1 + d2 * d2;

    float pen = (p4 - t2) * 4.0f;

    float lo_th = t2 * 0.95f;
    float lo_d  = p3 - lo_th;
    float lower = (p3 > p2) ? pen : ((p3 > lo_th) ? 0.0f : lo_d * lo_d);

    float up_th = t2 * 1.05f;
    float up_d  = p4 - up_th;
    float upper = (p4 < p2) ? pen : ((p4 < up_th) ? 0.0f : up_d * up_d);

    return main_mse + lower + upper;
}

// Warp-tile: 16 quads = 80 preds float4 (slots 0..79) + 48 target float4
// (slots 80..127) = 128 float4 = 2KB. Each lane issues 4 cp.async.
__device__ __forceinline__ void stage_wtile(uint32_t saddr,
                                            const float4* __restrict__ preds4,
                                            const float4* __restrict__ tgt4,
                                            int t, int lane)
{
    const float4* pg = preds4 + (size_t)t * 80;
    const float4* tg = tgt4   + (size_t)t * 48;

    cp_async16(saddr + (uint32_t)lane * 16u,         pg + lane);        // 0..31
    cp_async16(saddr + (uint32_t)(32 + lane) * 16u,  pg + 32 + lane);   // 32..63
    {
        int s64 = 64 + lane;                                             // 64..95
        const float4* src = (s64 < 80) ? (pg + s64) : (tg + (s64 - 80));
        cp_async16(saddr + (uint32_t)s64 * 16u, src);
    }
    cp_async16(saddr + (uint32_t)(96 + lane) * 16u,  tg + 16 + lane);   // 96..127

    asm volatile("cp.async.commit_group;\n" ::: "memory");
}

__global__ void __launch_bounds__(256)
quantile_loss_kernel(const float4* __restrict__ preds4,
                     const float4* __restrict__ tgt4,
                     const float*  __restrict__ preds,
                     const float*  __restrict__ target,
                     float* __restrict__ out,
                     int nquads, int n_rows, float inv_count)
{
    __shared__ float4 sh[2048];      // 8 warps * 2 buffers * 128 float4 = 32KB
    __shared__ float  warp_sums[8];

    const int tid  = threadIdx.x;
    const int lane = tid & 31;
    const int wid  = tid >> 5;

    float4*  wbuf   = sh + wid * 256;   // this warp's two buffers
    uint32_t wsaddr = (uint32_t)__cvta_generic_to_shared(wbuf);

    const int n_wt     = nquads >> 4;                 // full 16-quad warp tiles
    const int wt0      = ((int)blockIdx.x << 3) + wid;
    const int wstride  = (int)gridDim.x << 3;

    float s = 0.0f;

    // prologue: prefetch first warp-tile into buffer 0
    if (wt0 < n_wt)
        stage_wtile(wsaddr, preds4, tgt4, wt0, lane);

    const int p = lane >> 1;          // quad pair index 0..15
    int buf = 0;

    for (int t = wt0; t < n_wt; t += wstride) {
        int next = t + wstride;
        __syncwarp();                 // prior reads of buf^1 done before refill
        if (next < n_wt) {
            stage_wtile(wsaddr + (uint32_t)(buf ^ 1) * 128u * 16u,
                        preds4, tgt4, next, lane);
            asm volatile("cp.async.wait_group 1;\n" ::: "memory");
        } else {
            asm volatile("cp.async.wait_group 0;\n" ::: "memory");
        }
        __syncwarp();                 // all lanes' copies for buf complete

        const float4* b = wbuf + buf * 128;
        if (!(lane & 1)) {
            // rows 0,1 of quad p
            float4 P0 = b[p * 5 + 0];
            float4 P1 = b[p * 5 + 1];
            float4 P2 = b[p * 5 + 2];
            float4 G0 = b[80 + p * 3 + 0];
            float4 G1 = b[80 + p * 3 + 1];
            s += row_loss(P0.x, P0.y, P0.z, P0.w, P1.x, G0.x, G0.y, G0.z);
            s += row_loss(P1.y, P1.z, P1.w, P2.x, P2.y, G0.w, G1.x, G1.y);
        } else {
            // rows 2,3 of quad p
            float4 P2 = b[p * 5 + 2];
            float4 P3 = b[p * 5 + 3];
            float4 P4 = b[p * 5 + 4];
            float4 G1 = b[80 + p * 3 + 1];
            float4 G2 = b[80 + p * 3 + 2];
            s += row_loss(P2.z, P2.w, P3.x, P3.y, P3.z, G1.z, G1.w, G2.x);
            s += row_loss(P3.w, P4.x, P4.y, P4.z, P4.w, G2.y, G2.z, G2.w);
        }
        buf ^= 1;
    }

    // remainder quads (nquads % 16): block 0, direct loads
    if (blockIdx.x == 0) {
        int rq = (n_wt << 4) + tid;
        if (rq < nquads) {
            float4 p0 = preds4[rq * 5 + 0];
            float4 p1 = preds4[rq * 5 + 1];
            float4 p2 = preds4[rq * 5 + 2];
            float4 p3 = preds4[rq * 5 + 3];
            float4 p4 = preds4[rq * 5 + 4];
            float4 g0 = tgt4[rq * 3 + 0];
            float4 g1 = tgt4[rq * 3 + 1];
            float4 g2 = tgt4[rq * 3 + 2];
            s += row_loss(p0.x, p0.y, p0.z, p0.w, p1.x, g0.x, g0.y, g0.z);
            s += row_loss(p1.y, p1.z, p1.w, p2.x, p2.y, g0.w, g1.x, g1.y);
            s += row_loss(p2.z, p2.w, p3.x, p3.y, p3.z, g1.z, g1.w, g2.x);
            s += row_loss(p3.w, p4.x, p4.y, p4.z, p4.w, g2.y, g2.z, g2.w);
        }
        // tail rows (n_rows % 4)
        if (tid == 0) {
            for (int r = nquads * 4; r < n_rows; r++) {
                s += row_loss(preds[r * 5 + 0], preds[r * 5 + 1], preds[r * 5 + 2],
                              preds[r * 5 + 3], preds[r * 5 + 4],
                              target[r * 3 + 0], target[r * 3 + 1], target[r * 3 + 2]);
            }
        }
    }

    // intra-block reduce: warp shuffle -> warp_sums -> warp 0 -> atomicAdd
    #pragma unroll
    for (int off = 16; off > 0; off >>= 1)
        s += __shfl_down_sync(0xFFFFFFFFu, s, off);

    if (lane == 0) warp_sums[wid] = s;
    __syncthreads();

    if (wid == 0) {
        s = (lane < 8) ? warp_sums[lane] : 0.0f;
        #pragma unroll
        for (int off = 4; off > 0; off >>= 1)
            s += __shfl_down_sync(0xFFFFFFFFu, s, off);
        if (lane == 0)
            atomicAdd(out, s * inv_count);
    }
}

extern "C" void kernel_launch(void* const* d_in, const int* in_sizes, int n_in,
                              void* d_out, int out_size)
{
    const float* preds  = (const float*)d_in[0];
    const float* target = (const float*)d_in[1];
    float* out = (float*)d_out;

    int n_rows = in_sizes[0] / 5;
    int nquads = n_rows / 4;
    float inv_count = 1.0f / (5.0f * (float)n_rows);

    zero_out_kernel<<<1, 32>>>(out);

    const int threads = 256;
    int n_wt = nquads >> 4;
    int blocks = 6 * 148;                       // persistent: 6 CTAs/SM
    int need = (n_wt + 7) / 8;
    if (need > 0 && need < blocks) blocks = need;
    if (blocks < 1) blocks = 1;

    quantile_loss_kernel<<<blocks, threads>>>(
        (const float4*)preds, (const float4*)target,
        preds, target, out, nquads, n_rows, inv_count);
}

// round 17
// speedup vs baseline: 1.0808x; 1.0808x over previous
#include <cuda_runtime.h>
#include <cstdint>

// QuantileLoss: mean over [N,5] loss built from preds[N,5], target[N,3].
// FINAL (= R4, verified 3x: 25.056us bench / 22.7-23.2us kernel / rel_err 0.0):
//   cp.async-staged 32KB smem tiles for perfect per-LDG coalescing.
//   Direct loads have 80B/48B lane strides (~20 lines per LDG.128) -> L1tex
//   wavefront-limited at 72% DRAM; staging lifts to 76.5% DRAM / 6063 GB/s,
//   ~96% of the B300 path-independent LTS cap (~6300 B/cyc).
// Exhaustively verified dead ends (16 rounds):
//   - block-coupled double buffers (R5/R6/R8): occupancy or barrier-convoy tax
//   - per-warp barrier-free pipeline (R16): per-stage issue overhead (45% issue)
//   - single-node epilogues, any flavor (R3/R10/R11): -8% DRAM each
//   - TMA bulk (R13): identical to cp.async at the LTS cap
//   - L2 prefetch-ahead (R14): doubles LTS traffic, -9% DRAM
//   - __ldcs, reg caps, 2-quads/thread (R2/R7): neutral or negative

__global__ void zero_out_kernel(float* out) {
    if (threadIdx.x == 0) out[0] = 0.0f;
}

__device__ __forceinline__ void cp_async16(uint32_t saddr, const void* gptr) {
    asm volatile("cp.async.cg.shared.global [%0], [%1], 16;\n"
                 :: "r"(saddr), "l"(gptr));
}

__device__ __forceinline__ float row_loss(
    float p0, float p1, float p2, float p3, float p4,
    float t0, float t1, float t2)
{
    float d0 = p0 - t0;
    float d1 = p1 - t1;
    float d2 = p2 - t2;
    float main_mse = d0 * d0 + d1 * d1 + d2 * d2;

    float pen = (p4 - t2) * 4.0f;

    float lo_th = t2 * 0.95f;
    float lo_d  = p3 - lo_th;
    float lower = (p3 > p2) ? pen : ((p3 > lo_th) ? 0.0f : lo_d * lo_d);

    float up_th = t2 * 1.05f;
    float up_d  = p4 - up_th;
    float upper = (p4 < p2) ? pen : ((p4 < up_th) ? 0.0f : up_d * up_d);

    return main_mse + lower + upper;
}

__device__ __forceinline__ float quad_rows(
    float4 p0, float4 p1, float4 p2, float4 p3, float4 p4,
    float4 g0, float4 g1, float4 g2)
{
    float s;
    s  = row_loss(p0.x, p0.y, p0.z, p0.w, p1.x, g0.x, g0.y, g0.z);
    s += row_loss(p1.y, p1.z, p1.w, p2.x, p2.y, g0.w, g1.x, g1.y);
    s += row_loss(p2.z, p2.w, p3.x, p3.y, p3.z, g1.z, g1.w, g2.x);
    s += row_loss(p3.w, p4.x, p4.y, p4.z, p4.w, g2.y, g2.z, g2.w);
    return s;
}

// Tile: 256 quads (= 1024 rows) per block of 256 threads.
// smem: 1280 float4 preds + 768 float4 target = 2048 float4 = 32 KB exactly.
__global__ void __launch_bounds__(256)
quantile_loss_kernel(const float4* __restrict__ preds4,
                     const float4* __restrict__ tgt4,
                     const float*  __restrict__ preds,
                     const float*  __restrict__ target,
                     float* __restrict__ out,
                     int nquads, int n_rows, float inv_count)
{
    __shared__ float4 sh[2048];   // [0..1279] preds, [1280..2047] target

    const int tid = threadIdx.x;
    const int qb  = blockIdx.x << 8;   // 256 quads per block
    float s = 0.0f;

    if (qb + 256 <= nquads) {
        // ---- fast path: fully-coalesced cp.async staging ----
        uint32_t sbase = (uint32_t)__cvta_generic_to_shared(sh);
        const float4* pg = preds4 + (size_t)qb * 5;
        const float4* tg = tgt4   + (size_t)qb * 3;

        #pragma unroll
        for (int k = 0; k < 5; k++)
            cp_async16(sbase + (uint32_t)(k * 256 + tid) * 16u, pg + k * 256 + tid);
        #pragma unroll
        for (int k = 0; k < 3; k++)
            cp_async16(sbase + (uint32_t)(1280 + k * 256 + tid) * 16u, tg + k * 256 + tid);

        asm volatile("cp.async.commit_group;\n" ::: "memory");
        asm volatile("cp.async.wait_group 0;\n" ::: "memory");
        __syncthreads();

        // strided smem reads: 80B / 48B lane strides are conflict-free
        float4 p0 = sh[tid * 5 + 0];
        float4 p1 = sh[tid * 5 + 1];
        float4 p2 = sh[tid * 5 + 2];
        float4 p3 = sh[tid * 5 + 3];
        float4 p4 = sh[tid * 5 + 4];
        float4 g0 = sh[1280 + tid * 3 + 0];
        float4 g1 = sh[1280 + tid * 3 + 1];
        float4 g2 = sh[1280 + tid * 3 + 2];

        s = quad_rows(p0, p1, p2, p3, p4, g0, g1, g2);
    } else {
        // ---- partial tile: direct guarded loads (rare) ----
        int q = qb + tid;
        if (q < nquads) {
            float4 p0 = preds4[q * 5 + 0];
            float4 p1 = preds4[q * 5 + 1];
            float4 p2 = preds4[q * 5 + 2];
            float4 p3 = preds4[q * 5 + 3];
            float4 p4 = preds4[q * 5 + 4];
            float4 g0 = tgt4[q * 3 + 0];
            float4 g1 = tgt4[q * 3 + 1];
            float4 g2 = tgt4[q * 3 + 2];
            s = quad_rows(p0, p1, p2, p3, p4, g0, g1, g2);
        }
    }

    // tail rows (n_rows % 4) handled by one thread
    if (blockIdx.x == 0 && threadIdx.x == 0) {
        for (int r = nquads * 4; r < n_rows; r++) {
            s += row_loss(preds[r * 5 + 0], preds[r * 5 + 1], preds[r * 5 + 2],
                          preds[r * 5 + 3], preds[r * 5 + 4],
                          target[r * 3 + 0], target[r * 3 + 1], target[r * 3 + 2]);
        }
    }

    // intra-block reduce: warp shuffle -> smem (reuse tile) -> warp 0
    #pragma unroll
    for (int off = 16; off > 0; off >>= 1)
        s += __shfl_down_sync(0xFFFFFFFFu, s, off);

    __syncthreads();                      // all smem tile reads done
    float* ws = (float*)sh;               // reuse tile as warp-sum scratch
    int lane = tid & 31;
    int wid  = tid >> 5;
    if (lane == 0) ws[wid] = s;
    __syncthreads();

    if (wid == 0) {
        s = (lane < 8) ? ws[lane] : 0.0f;
        #pragma unroll
        for (int off = 4; off > 0; off >>= 1)
            s += __shfl_down_sync(0xFFFFFFFFu, s, off);
        if (lane == 0)
            atomicAdd(out, s * inv_count);
    }
}

extern "C" void kernel_launch(void* const* d_in, const int* in_sizes, int n_in,
                              void* d_out, int out_size)
{
    const float* preds  = (const float*)d_in[0];
    const float* target = (const float*)d_in[1];
    float* out = (float*)d_out;

    int n_rows = in_sizes[0] / 5;
    int nquads = n_rows / 4;
    float inv_count = 1.0f / (5.0f * (float)n_rows);

    zero_out_kernel<<<1, 32>>>(out);

    const int threads = 256;
    int blocks = (nquads + 255) / 256;
    if (blocks < 1) blocks = 1;

    quantile_loss_kernel<<<blocks, threads>>>(
        (const float4*)preds, (const float4*)target,
        preds, target, out, nquads, n_rows, inv_count);
}